// round 1
// baseline (speedup 1.0000x reference)
#include <cuda_runtime.h>
#include <math.h>

#define NPTS 8192
#define BATCH 2
#define VOXD 64
#define VOXH 128
#define VOXW 128
#define VOX (VOXD*VOXH*VOXW)
#define DPIX (512*512)
#define CTB 128

// Scratch (no allocations allowed -> device globals)
__device__ float g_min[2 * BATCH * NPTS];   // [dir][b][n] per-point min sq dist
__device__ float g_cl[BATCH * 512 * 3];     // cldice partials: inter, psum, gsum
__device__ float g_dp[BATCH * 128 * 6];     // depth partials: g, g2, gx, gy, l1, mask

// ---------------------------------------------------------------------------
// Chamfer: for each point in A, min squared distance to all points in B.
// dir==0: A=pred, B=gt ; dir==1: A=gt, B=pred. (N == M == 8192)
// ---------------------------------------------------------------------------
__global__ void nn_min_kernel(const float* __restrict__ pc,
                              const float* __restrict__ gp) {
    __shared__ float4 spt[CTB];
    const int dir = blockIdx.z;
    const int b = blockIdx.y;
    const float* A  = (dir == 0 ? pc : gp) + (size_t)b * NPTS * 3;
    const float* Bp = (dir == 0 ? gp : pc) + (size_t)b * NPTS * 3;

    const int i = blockIdx.x * CTB + threadIdx.x;
    const float px = A[i * 3 + 0];
    const float py = A[i * 3 + 1];
    const float pz = A[i * 3 + 2];

    float best = 3.402823e38f;
    for (int t0 = 0; t0 < NPTS; t0 += CTB) {
        const int j = t0 + threadIdx.x;
        spt[threadIdx.x] = make_float4(Bp[j * 3 + 0], Bp[j * 3 + 1], Bp[j * 3 + 2], 0.f);
        __syncthreads();
#pragma unroll 16
        for (int k = 0; k < CTB; k++) {
            const float4 q = spt[k];
            const float dx = px - q.x;
            const float dy = py - q.y;
            const float dz = pz - q.z;
            const float d = fmaf(dx, dx, fmaf(dy, dy, dz * dz));
            best = fminf(best, d);
        }
        __syncthreads();
    }
    g_min[(dir * BATCH + b) * NPTS + i] = best;
}

// ---------------------------------------------------------------------------
// clDice partial sums. erode3d = 3x3x3 min with clamped (SAME) window.
// sigmoid is monotone increasing -> erode(sigmoid(x)) == sigmoid(erode(x)).
// ---------------------------------------------------------------------------
__global__ void cldice_kernel(const float* __restrict__ pv,
                              const float* __restrict__ gv) {
    const int b = blockIdx.y;
    const float* P = pv + (size_t)b * VOX;
    const float* G = gv + (size_t)b * VOX;

    float si = 0.f, sp = 0.f, sg = 0.f;
    const int base = blockIdx.x * (256 * 8);
#pragma unroll
    for (int k = 0; k < 8; k++) {
        const int idx = base + k * 256 + threadIdx.x;
        const int w = idx & (VOXW - 1);
        const int h = (idx >> 7) & (VOXH - 1);
        const int d = idx >> 14;
        const int d0 = d > 0 ? d - 1 : 0;
        const int d1 = d < VOXD - 1 ? d + 1 : d;
        const int h0 = h > 0 ? h - 1 : 0;
        const int h1 = h < VOXH - 1 ? h + 1 : h;
        const int w0 = w > 0 ? w - 1 : 0;
        const int w1 = w < VOXW - 1 ? w + 1 : w;

        float pmin = 3.402823e38f, gmin = 3.402823e38f;
        for (int dd = d0; dd <= d1; dd++) {
            for (int hh = h0; hh <= h1; hh++) {
                const int rowoff = (dd * VOXH + hh) * VOXW;
#pragma unroll
                for (int ww = w0; ww <= w1; ww++) {
                    pmin = fminf(pmin, __ldg(P + rowoff + ww));
                    gmin = fminf(gmin, __ldg(G + rowoff + ww));
                }
            }
        }
        const float ps = 1.f / (1.f + expf(-pmin));
        si = fmaf(ps, gmin, si);
        sp += ps;
        sg += gmin;
    }

    __shared__ float red[256];
    float v[3] = {si, sp, sg};
    for (int q = 0; q < 3; q++) {
        red[threadIdx.x] = v[q];
        __syncthreads();
        for (int s = 128; s > 0; s >>= 1) {
            if (threadIdx.x < s) red[threadIdx.x] += red[threadIdx.x + s];
            __syncthreads();
        }
        if (threadIdx.x == 0) g_cl[(b * 512 + blockIdx.x) * 3 + q] = red[0];
        __syncthreads();
    }
}

// ---------------------------------------------------------------------------
// Depth loss partial sums: SILog terms, gradient L1, masked L1.
// ---------------------------------------------------------------------------
__global__ void depth_kernel(const float* __restrict__ pd,
                             const float* __restrict__ gd,
                             const float* __restrict__ mk) {
    const int b = blockIdx.y;
    const float* P = pd + (size_t)b * DPIX;
    const float* G = gd + (size_t)b * DPIX;
    const float* M = mk + (size_t)b * DPIX;

    float s[6] = {0.f, 0.f, 0.f, 0.f, 0.f, 0.f};
    const int base = blockIdx.x * (256 * 8);
#pragma unroll
    for (int k = 0; k < 8; k++) {
        const int idx = base + k * 256 + threadIdx.x;
        const int h = idx >> 9;
        const int w = idx & 511;
        const float p = P[idx];
        const float g = G[idx];
        const float lg = logf(p + 0.1f) - logf(g + 0.1f);
        s[0] += lg;
        s[1] = fmaf(lg, lg, s[1]);
        if (h < 511) {
            const float a = fabsf(p - P[idx + 512]);
            const float c = fabsf(g - G[idx + 512]);
            s[2] += fabsf(a - c);
        }
        if (w < 511) {
            const float a = fabsf(p - P[idx + 1]);
            const float c = fabsf(g - G[idx + 1]);
            s[3] += fabsf(a - c);
        }
        const float m = M[idx];
        s[4] += fabsf(p - g) * m;
        s[5] += m;
    }

    __shared__ float red[256];
    for (int q = 0; q < 6; q++) {
        red[threadIdx.x] = s[q];
        __syncthreads();
        for (int st = 128; st > 0; st >>= 1) {
            if (threadIdx.x < st) red[threadIdx.x] += red[threadIdx.x + st];
            __syncthreads();
        }
        if (threadIdx.x == 0) g_dp[(b * 128 + blockIdx.x) * 6 + q] = red[0];
        __syncthreads();
    }
}

// ---------------------------------------------------------------------------
// Final combine: deterministic single-block reductions + scalar formula.
// ---------------------------------------------------------------------------
__device__ __forceinline__ float block_sum(float v, float* red, int tid) {
    red[tid] = v;
    __syncthreads();
    for (int s = 256; s > 0; s >>= 1) {
        if (tid < s) red[tid] += red[tid + s];
        __syncthreads();
    }
    const float r = red[0];
    __syncthreads();
    return r;
}

__global__ void finalize_kernel(const int* __restrict__ iter,
                                float* __restrict__ out) {
    __shared__ float red[512];
    const int tid = threadIdx.x;

    // chamfer sums (each direction: BATCH*NPTS mins)
    float sa = 0.f, sb = 0.f;
    for (int i = tid; i < BATCH * NPTS; i += 512) {
        sa += g_min[i];
        sb += g_min[BATCH * NPTS + i];
    }
    sa = block_sum(sa, red, tid);
    sb = block_sum(sb, red, tid);

    // cldice sums
    float inter[BATCH], psum[BATCH], gsum[BATCH];
    for (int b = 0; b < BATCH; b++) {
        float vi = g_cl[(b * 512 + tid) * 3 + 0];
        float vp = g_cl[(b * 512 + tid) * 3 + 1];
        float vg = g_cl[(b * 512 + tid) * 3 + 2];
        inter[b] = block_sum(vi, red, tid);
        psum[b]  = block_sum(vp, red, tid);
        gsum[b]  = block_sum(vg, red, tid);
    }

    // depth sums
    float ds[BATCH][6];
    for (int b = 0; b < BATCH; b++) {
        for (int q = 0; q < 6; q++) {
            const float v = (tid < 128) ? g_dp[(b * 128 + tid) * 6 + q] : 0.f;
            ds[b][q] = block_sum(v, red, tid);
        }
    }

    if (tid == 0) {
        const float chamfer = sa / (float)(BATCH * NPTS) + sb / (float)(BATCH * NPTS);

        float dice_acc = 0.f;
        for (int b = 0; b < BATCH; b++) {
            dice_acc += (2.f * inter[b] + 1e-5f) / (psum[b] + gsum[b] + 1e-5f);
        }
        const float cldice = 1.f - dice_acc / (float)BATCH;

        float var_acc = 0.f, m2_acc = 0.f;
        for (int b = 0; b < BATCH; b++) {
            const float mean = ds[b][0] / (float)DPIX;
            const float var = ds[b][1] / (float)DPIX - mean * mean;
            var_acc += var;
            m2_acc += mean * mean;
        }
        const float silog = 10.f * (var_acc / (float)BATCH) + 10.f * (m2_acc / (float)BATCH);

        const float gx = ds[0][2] + ds[1][2];
        const float gy = ds[0][3] + ds[1][3];
        const float grad_l1 = gx / (float)(BATCH * 511 * 512) + gy / (float)(BATCH * 512 * 511);

        const float mask_l1 = (ds[0][4] + ds[1][4]) / (ds[0][5] + ds[1][5] + 1e-8f);

        const float dloss = silog + grad_l1 + mask_l1;

        int it = iter[0];
        if (it < 1) it = 1;
        const float gamma1 = 2.f * logf((float)it / 20000.f);

        out[0] = gamma1 * chamfer + 0.5f * cldice + 0.01f * dloss;
    }
}

extern "C" void kernel_launch(void* const* d_in, const int* in_sizes, int n_in,
                              void* d_out, int out_size) {
    const float* pc = (const float*)d_in[0];   // pred_centers [2,8192,3]
    const float* pv = (const float*)d_in[1];   // pred_volume  [2,1,64,128,128]
    const float* pd = (const float*)d_in[2];   // pred_depth   [2,512,512]
    const float* gp = (const float*)d_in[3];   // gt_points    [2,8192,3]
    const float* gv = (const float*)d_in[4];   // gt_volume    [2,1,64,128,128]
    const float* gd = (const float*)d_in[5];   // gt_depth     [2,512,512]
    const float* dm = (const float*)d_in[6];   // depth_mask   [2,512,512]
    const int* it   = (const int*)d_in[7];     // iteration (scalar)

    nn_min_kernel<<<dim3(NPTS / CTB, BATCH, 2), CTB>>>(pc, gp);
    cldice_kernel<<<dim3(VOX / (256 * 8), BATCH), 256>>>(pv, gv);
    depth_kernel<<<dim3(DPIX / (256 * 8), BATCH), 256>>>(pd, gd, dm);
    finalize_kernel<<<1, 512>>>(it, (float*)d_out);
}